// round 6
// baseline (speedup 1.0000x reference)
#include <cuda_runtime.h>
#include <cuda_bf16.h>
#include <math.h>
#include <stdint.h>

// Problem constants
#define NH 6
#define NN 64   // rows of A tile (n)
#define NK 64   // inner dim (k)
#define ND 30   // cols of B tile (d)

// ---------------- scratch (device globals) -----------------------------------
__device__ __align__(16) float g_amin[NH*NK], g_amax[NH*NK];
__device__ __align__(16) float g_bmin[NH*ND], g_bmax[NH*ND];
__device__ __align__(16) float g_dA[NH*NK], g_zA[NH*NK], g_iA[NH*NK];
__device__ __align__(16) float g_dB[NH*ND], g_zB[NH*ND], g_iB[NH*ND];

// ---------------- float atomic min/max via int/uint ordering -----------------
__device__ __forceinline__ void atomicMaxF(float* addr, float v) {
    if (v >= 0.0f) atomicMax((int*)addr, __float_as_int(v));
    else           atomicMin((unsigned int*)addr, __float_as_uint(v));
}
__device__ __forceinline__ void atomicMinF(float* addr, float v) {
    if (v >= 0.0f) atomicMin((int*)addr, __float_as_int(v));
    else           atomicMax((unsigned int*)addr, __float_as_uint(v));
}

// ---------------- small PTX helpers (base-target legal) ----------------------
__device__ __forceinline__ uint32_t smem_to_u32(const void* p) {
    uint32_t a;
    asm("{ .reg .u64 tmp; cvta.to.shared.u64 tmp, %1; cvt.u32.u64 %0, tmp; }"
        : "=r"(a) : "l"(p));
    return a;
}
__device__ __forceinline__ void ldsm_x4(uint32_t* r, uint32_t addr) {
    asm volatile("ldmatrix.sync.aligned.m8n8.x4.shared.b16 {%0,%1,%2,%3}, [%4];"
                 : "=r"(r[0]), "=r"(r[1]), "=r"(r[2]), "=r"(r[3]) : "r"(addr));
}
__device__ __forceinline__ void ldsm_x4_trans(uint32_t* r, uint32_t addr) {
    asm volatile("ldmatrix.sync.aligned.m8n8.x4.trans.shared.b16 {%0,%1,%2,%3}, [%4];"
                 : "=r"(r[0]), "=r"(r[1]), "=r"(r[2]), "=r"(r[3]) : "r"(addr));
}
__device__ __forceinline__ void mma_bf16(float* c, const uint32_t* a,
                                         const uint32_t* b) {
    asm volatile(
        "mma.sync.aligned.m16n8k16.row.col.f32.bf16.bf16.f32 "
        "{%0,%1,%2,%3}, {%4,%5,%6,%7}, {%8,%9}, {%0,%1,%2,%3};"
        : "+f"(c[0]), "+f"(c[1]), "+f"(c[2]), "+f"(c[3])
        : "r"(a[0]), "r"(a[1]), "r"(a[2]), "r"(a[3]), "r"(b[0]), "r"(b[1]));
}
#define SWZ128(off) ((off) ^ (((off) >> 3) & 0x70))

// ---------------- kernel 0: init minmax scratch ------------------------------
__global__ void k_init() {
    int i = threadIdx.x;
    if (i < NH*NK) { g_amin[i] =  INFINITY; g_amax[i] = -INFINITY; }
    if (i < NH*ND) { g_bmin[i] =  INFINITY; g_bmax[i] = -INFINITY; }
}

// ---------------- kernel 1a: min/max of A ------------------------------------
__global__ __launch_bounds__(256) void k_minmax_A(const float* __restrict__ A,
                                                  int batch, int bpb) {
    int h  = blockIdx.x;
    int b0 = blockIdx.y * bpb;
    int t  = threadIdx.x;
    int k0 = (t & 15) * 4;
    float4 mn = make_float4( INFINITY,  INFINITY,  INFINITY,  INFINITY);
    float4 mx = make_float4(-INFINITY, -INFINITY, -INFINITY, -INFINITY);
    for (int bi = 0; bi < bpb; ++bi) {
        int b = b0 + bi;
        if (b >= batch) break;
        const float4* p = (const float4*)(A + ((size_t)b * NH + h) * (NN*NK));
        #pragma unroll
        for (int it = 0; it < 4; ++it) {
            float4 v = p[it * 256 + t];
            mn.x = fminf(mn.x, v.x); mx.x = fmaxf(mx.x, v.x);
            mn.y = fminf(mn.y, v.y); mx.y = fmaxf(mx.y, v.y);
            mn.z = fminf(mn.z, v.z); mx.z = fmaxf(mx.z, v.z);
            mn.w = fminf(mn.w, v.w); mx.w = fmaxf(mx.w, v.w);
        }
    }
    __shared__ float smn[64*17], smx[64*17];
    int col = t >> 4;
    smn[(k0+0)*17 + col] = mn.x; smx[(k0+0)*17 + col] = mx.x;
    smn[(k0+1)*17 + col] = mn.y; smx[(k0+1)*17 + col] = mx.y;
    smn[(k0+2)*17 + col] = mn.z; smx[(k0+2)*17 + col] = mx.z;
    smn[(k0+3)*17 + col] = mn.w; smx[(k0+3)*17 + col] = mx.w;
    __syncthreads();
    if (t < 64) {
        float a = INFINITY, b = -INFINITY;
        #pragma unroll
        for (int c = 0; c < 16; ++c) {
            a = fminf(a, smn[t*17 + c]);
            b = fmaxf(b, smx[t*17 + c]);
        }
        atomicMinF(&g_amin[h*NK + t], a);
        atomicMaxF(&g_amax[h*NK + t], b);
    }
}

// ---------------- kernel 1b: min/max of B ------------------------------------
__global__ __launch_bounds__(480) void k_minmax_B(const float* __restrict__ B,
                                                  int batch, int bpb) {
    int h  = blockIdx.x;
    int b0 = blockIdx.y * bpb;
    int t  = threadIdx.x;
    float mn = INFINITY, mx = -INFINITY;
    for (int bi = 0; bi < bpb; ++bi) {
        int b = b0 + bi;
        if (b >= batch) break;
        const float* p = B + ((size_t)b * NH + h) * (NK*ND);
        #pragma unroll
        for (int it = 0; it < 4; ++it) {
            float v = p[it * 480 + t];
            mn = fminf(mn, v); mx = fmaxf(mx, v);
        }
    }
    __shared__ float smn[30*17], smx[30*17];
    int d = t % 30, g = t / 30;
    smn[d*17 + g] = mn; smx[d*17 + g] = mx;
    __syncthreads();
    if (t < 30) {
        float a = INFINITY, b = -INFINITY;
        #pragma unroll
        for (int c = 0; c < 16; ++c) {
            a = fminf(a, smn[t*17 + c]);
            b = fmaxf(b, smx[t*17 + c]);
        }
        atomicMinF(&g_bmin[h*ND + t], a);
        atomicMaxF(&g_bmax[h*ND + t], b);
    }
}

// ---------------- kernel 2: per-channel quant params -------------------------
__global__ void k_params() {
    int i = threadIdx.x;
    if (i < NH*NK) {
        float mn = g_amin[i], mx = g_amax[i];
        float d = fmaxf((mx - mn) / 255.0f, 1e-8f);
        float z = rintf(-mn / d);
        g_dA[i] = d; g_zA[i] = z; g_iA[i] = 1.0f / d;
    }
    if (i < NH*ND) {
        float mn = g_bmin[i], mx = g_bmax[i];
        float d = fmaxf((mx - mn) / 255.0f, 1e-8f);
        float z = rintf(-mn / d);
        g_dB[i] = d; g_zB[i] = z; g_iB[i] = 1.0f / d;
    }
}

// fake-quant (q-zp)*delta; fast reciprocal path, tie rescue via true division
__device__ __forceinline__ float fq(float x, float dlt, float zp, float inv) {
    float y = x * inv;
    float r = rintf(y);
    if (fabsf(fabsf(y - r) - 0.5f) < 1e-4f) r = rintf(x / dlt);
    float q = fminf(fmaxf(r + zp, 0.0f), 255.0f);
    return (q - zp) * dlt;
}
// fake-quant returning the integer (q-zp)  (exact in bf16, |v| <= 255)
__device__ __forceinline__ float fqi(float x, float dlt, float zp, float inv) {
    float y = x * inv;
    float r = rintf(y);
    if (fabsf(fabsf(y - r) - 0.5f) < 1e-4f) r = rintf(x / dlt);
    return fminf(fmaxf(r + zp, 0.0f), 255.0f) - zp;
}

__device__ __forceinline__ unsigned pack_bf16(__nv_bfloat16 lo, __nv_bfloat16 hi) {
    return (unsigned)__bfloat16_as_ushort(lo) | ((unsigned)__bfloat16_as_ushort(hi) << 16);
}

// ---------------- per-slice smem layout (bytes) ------------------------------
// Ahi: 64 rows(m) x 128B (bf16, SW128 swizzled)           = 8192
// Alo:                                                      8192
// Bt : 64 rows(k) x 80B stride (bf16 ints, d in 0..29)    = 5120
//      80B stride => ldmatrix 8-row phases hit disjoint banks
#define OFF_AHI 0
#define OFF_ALO 8192
#define OFF_BT  16384
#define B_STRIDE 80
#define SLICE_BYTES 21504
#define SMEM_DYN (2*SLICE_BYTES + 1024)

// ---------------- kernel 3: bf16 hi/lo split MMA quantized matmul ------------
// One block per PAIR of (b,h) slices; 8 warps, warps 0-3 slice0, 4-7 slice1.
// A stored [m][k] SW128; B stored k-major [k][d] (conflict-free stores),
// transposed at load time by ldmatrix.x4.trans.
__global__ __launch_bounds__(256)
void k_qmm_mma(const float* __restrict__ A, const float* __restrict__ B,
               float* __restrict__ C) {
    extern __shared__ char raw[];
    char* sm = (char*)(((uintptr_t)raw + 1023) & ~(uintptr_t)1023);
    uint32_t sb = smem_to_u32(sm);

    int t = threadIdx.x;
    int p = blockIdx.x;
    int s0 = 2 * p;
    int h0 = s0 % NH, h1 = (s0 + 1) % NH;

    // ---- A: quantize, hi/lo split, swizzled store ----
    // k0 = (4t)&63 is invariant across iterations; params hoisted per half.
    const float4* Ap = (const float4*)(A + (size_t)s0 * (NN*NK));
    int k0 = (4 * t) & 63;
    #pragma unroll
    for (int j = 0; j < 2; ++j) {
        int hb = (j ? h1 : h0) * NK + k0;
        float4 d4 = __ldg((const float4*)&g_dA[hb]);
        float4 z4 = __ldg((const float4*)&g_zA[hb]);
        float4 i4 = __ldg((const float4*)&g_iA[hb]);
        char* base = sm + j * SLICE_BYTES;
        #pragma unroll
        for (int it = 0; it < 4; ++it) {
            int idx = (j * 4 + it) * 256 + t;
            float4 v = Ap[idx];
            int m = (idx & 1023) >> 4;
            float q0 = fq(v.x, d4.x, z4.x, i4.x);
            float q1 = fq(v.y, d4.y, z4.y, i4.y);
            float q2 = fq(v.z, d4.z, z4.z, i4.z);
            float q3 = fq(v.w, d4.w, z4.w, i4.w);
            __nv_bfloat16 h0b = __float2bfloat16(q0), h1b = __float2bfloat16(q1);
            __nv_bfloat16 h2b = __float2bfloat16(q2), h3b = __float2bfloat16(q3);
            __nv_bfloat16 l0b = __float2bfloat16(q0 - __bfloat162float(h0b));
            __nv_bfloat16 l1b = __float2bfloat16(q1 - __bfloat162float(h1b));
            __nv_bfloat16 l2b = __float2bfloat16(q2 - __bfloat162float(h2b));
            __nv_bfloat16 l3b = __float2bfloat16(q3 - __bfloat162float(h3b));
            uint32_t off = SWZ128((uint32_t)(m * 128 + k0 * 2));
            *(uint2*)(base + OFF_AHI + off) =
                make_uint2(pack_bf16(h0b, h1b), pack_bf16(h2b, h3b));
            *(uint2*)(base + OFF_ALO + off) =
                make_uint2(pack_bf16(l0b, l1b), pack_bf16(l2b, l3b));
        }
    }

    // ---- B: quantize to exact bf16 integers, k-major store (no transpose) ---
    // store addr = k*80 + d*2 : consecutive lanes -> consecutive bytes
    const float* Bp = B + (size_t)s0 * (NK*ND);
    #pragma unroll
    for (int it = 0; it < 15; ++it) {
        int e = it * 256 + t;
        float x = Bp[e];
        int j  = (e >= NK*ND);
        int e2 = e - j * (NK*ND);
        int k  = e2 / ND, d = e2 % ND;
        int hb = (j ? h1 : h0) * ND + d;
        float bi = fqi(x, __ldg(&g_dB[hb]), __ldg(&g_zB[hb]), __ldg(&g_iB[hb]));
        *(__nv_bfloat16*)(sm + j * SLICE_BYTES + OFF_BT + k * B_STRIDE + d * 2) =
            __float2bfloat16(bi);
    }
    __syncthreads();

    // ---- compute: warp = 16 rows x 32 cols, mma.sync m16n8k16 bf16 ----
    int w = t >> 5, lane = t & 31;
    int sj = w >> 2;          // slice
    int ws = w & 3;           // warp within slice
    int r0 = ws * 16;
    uint32_t baseS = sb + sj * SLICE_BYTES;

    int la = lane & 7, lb = (lane >> 3) & 1, lc = (lane >> 4) & 1;
    // A x4 (non-trans): rows r0+la+8*lb, col byte 16*lc (k0 / k0+8)
    uint32_t aRel = (uint32_t)((r0 + la + lb * 8) * 128 + lc * 16);
    // B x4 trans addressing on k-major tile:
    //   matrix g = (lc,lb): rows k = 8*lb + la, col byte = 16*lc
    //   -> regs: r0=b0(d0..7), r1=b1(d0..7), r2=b0(d8..15), r3=b1(d8..15)
    uint32_t bRow = (uint32_t)(lb * 8 + la);         // k within 16-tile
    uint32_t bCol = (uint32_t)(lc * 16);             // d-block byte offset

    float acc[4][4];
    #pragma unroll
    for (int i = 0; i < 4; ++i)
        #pragma unroll
        for (int q = 0; q < 4; ++q) acc[i][q] = 0.0f;

    #pragma unroll
    for (int kt = 0; kt < 4; ++kt) {
        uint32_t ah[4], al[4], b0[4], b1[4];
        uint32_t ao = SWZ128(aRel + kt * 32);
        ldsm_x4(ah, baseS + OFF_AHI + ao);
        ldsm_x4(al, baseS + OFF_ALO + ao);
        uint32_t brow = baseS + OFF_BT + (kt * 16 + bRow) * B_STRIDE + bCol;
        ldsm_x4_trans(b0, brow);        // d 0..15
        ldsm_x4_trans(b1, brow + 32);   // d 16..31
        mma_bf16(acc[0], ah, b0 + 0); mma_bf16(acc[0], al, b0 + 0);
        mma_bf16(acc[1], ah, b0 + 2); mma_bf16(acc[1], al, b0 + 2);
        mma_bf16(acc[2], ah, b1 + 0); mma_bf16(acc[2], al, b1 + 0);
        mma_bf16(acc[3], ah, b1 + 2); mma_bf16(acc[3], al, b1 + 2);
    }

    // ---- epilogue: scale by dB[d], write C ----
    int s  = s0 + sj;
    int h  = s % NH;
    int row = r0 + (lane >> 2);
    int dd  = 2 * (lane & 3);
    float* Cp = C + (size_t)s * (NN*ND);
    #pragma unroll
    for (int nt = 0; nt < 4; ++nt) {
        int d = nt * 8 + dd;
        if (d < ND) {
            float sc0 = __ldg(&g_dB[h*ND + d]);
            Cp[row * ND + d]       = acc[nt][0] * sc0;
            Cp[(row + 8) * ND + d] = acc[nt][2] * sc0;
            if (d + 1 < ND) {
                float sc1 = __ldg(&g_dB[h*ND + d + 1]);
                Cp[row * ND + d + 1]       = acc[nt][1] * sc1;
                Cp[(row + 8) * ND + d + 1] = acc[nt][3] * sc1;
            }
        }
    }
}

// ---------------- launch -----------------------------------------------------
extern "C" void kernel_launch(void* const* d_in, const int* in_sizes, int n_in,
                              void* d_out, int out_size) {
    const float* A = (const float*)d_in[0];
    const float* B = (const float*)d_in[1];
    float* C = (float*)d_out;

    int batch  = in_sizes[0] / (NH * NN * NK);   // 4096
    int npairs = batch * NH / 2;                 // 12288

    k_init<<<1, 384>>>();

    int bpbA = 32;
    int nbyA = (batch + bpbA - 1) / bpbA;
    k_minmax_A<<<dim3(NH, nbyA), 256>>>(A, batch, bpbA);

    int bpbB = 64;
    int nbyB = (batch + bpbB - 1) / bpbB;
    k_minmax_B<<<dim3(NH, nbyB), 480>>>(B, batch, bpbB);

    k_params<<<1, 384>>>();

    cudaFuncSetAttribute(k_qmm_mma, cudaFuncAttributeMaxDynamicSharedMemorySize,
                         SMEM_DYN);
    k_qmm_mma<<<npairs, 256, SMEM_DYN>>>(A, B, C);
}

// round 7
// speedup vs baseline: 1.1126x; 1.1126x over previous
#include <cuda_runtime.h>
#include <cuda_bf16.h>
#include <math.h>
#include <stdint.h>

// Problem constants
#define NH 6
#define NN 64   // rows of A tile (n)
#define NK 64   // inner dim (k)
#define ND 30   // cols of B tile (d)

// ---------------- scratch (device globals) -----------------------------------
__device__ __align__(16) float g_amin[NH*NK], g_amax[NH*NK];
__device__ __align__(16) float g_bmin[NH*ND], g_bmax[NH*ND];
__device__ __align__(16) float g_dA[NH*NK], g_zA[NH*NK], g_iA[NH*NK];
__device__ __align__(16) float g_dB[NH*ND], g_zB[NH*ND], g_iB[NH*ND];

// ---------------- float atomic min/max via int/uint ordering -----------------
__device__ __forceinline__ void atomicMaxF(float* addr, float v) {
    if (v >= 0.0f) atomicMax((int*)addr, __float_as_int(v));
    else           atomicMin((unsigned int*)addr, __float_as_uint(v));
}
__device__ __forceinline__ void atomicMinF(float* addr, float v) {
    if (v >= 0.0f) atomicMin((int*)addr, __float_as_int(v));
    else           atomicMax((unsigned int*)addr, __float_as_uint(v));
}

// ---------------- small PTX helpers (base-target legal) ----------------------
__device__ __forceinline__ uint32_t smem_to_u32(const void* p) {
    uint32_t a;
    asm("{ .reg .u64 tmp; cvta.to.shared.u64 tmp, %1; cvt.u32.u64 %0, tmp; }"
        : "=r"(a) : "l"(p));
    return a;
}
__device__ __forceinline__ void ldsm_x4(uint32_t* r, uint32_t addr) {
    asm volatile("ldmatrix.sync.aligned.m8n8.x4.shared.b16 {%0,%1,%2,%3}, [%4];"
                 : "=r"(r[0]), "=r"(r[1]), "=r"(r[2]), "=r"(r[3]) : "r"(addr));
}
__device__ __forceinline__ void mma_bf16(float* c, const uint32_t* a,
                                         const uint32_t* b) {
    asm volatile(
        "mma.sync.aligned.m16n8k16.row.col.f32.bf16.bf16.f32 "
        "{%0,%1,%2,%3}, {%4,%5,%6,%7}, {%8,%9}, {%0,%1,%2,%3};"
        : "+f"(c[0]), "+f"(c[1]), "+f"(c[2]), "+f"(c[3])
        : "r"(a[0]), "r"(a[1]), "r"(a[2]), "r"(a[3]), "r"(b[0]), "r"(b[1]));
}
#define SWZ128(off) ((off) ^ (((off) >> 3) & 0x70))

// round-to-nearest-even via magic constant (valid |y| < 2^22); 2 FADDs
__device__ __forceinline__ float rne(float y) {
    const float M = 12582912.0f;   // 1.5 * 2^23
    return __fadd_rn(__fadd_rn(y, M), -M);
}

// ---------------- kernel 0: init minmax scratch ------------------------------
__global__ void k_init() {
    int i = threadIdx.x;
    if (i < NH*NK) { g_amin[i] =  INFINITY; g_amax[i] = -INFINITY; }
    if (i < NH*ND) { g_bmin[i] =  INFINITY; g_bmax[i] = -INFINITY; }
}

// ---------------- kernel 1a: min/max of A ------------------------------------
__global__ __launch_bounds__(256) void k_minmax_A(const float* __restrict__ A,
                                                  int batch, int bpb) {
    int h  = blockIdx.x;
    int b0 = blockIdx.y * bpb;
    int t  = threadIdx.x;
    int k0 = (t & 15) * 4;
    float4 mn = make_float4( INFINITY,  INFINITY,  INFINITY,  INFINITY);
    float4 mx = make_float4(-INFINITY, -INFINITY, -INFINITY, -INFINITY);
    for (int bi = 0; bi < bpb; ++bi) {
        int b = b0 + bi;
        if (b >= batch) break;
        const float4* p = (const float4*)(A + ((size_t)b * NH + h) * (NN*NK));
        #pragma unroll
        for (int it = 0; it < 4; ++it) {
            float4 v = p[it * 256 + t];
            mn.x = fminf(mn.x, v.x); mx.x = fmaxf(mx.x, v.x);
            mn.y = fminf(mn.y, v.y); mx.y = fmaxf(mx.y, v.y);
            mn.z = fminf(mn.z, v.z); mx.z = fmaxf(mx.z, v.z);
            mn.w = fminf(mn.w, v.w); mx.w = fmaxf(mx.w, v.w);
        }
    }
    __shared__ float smn[64*17], smx[64*17];
    int col = t >> 4;
    smn[(k0+0)*17 + col] = mn.x; smx[(k0+0)*17 + col] = mx.x;
    smn[(k0+1)*17 + col] = mn.y; smx[(k0+1)*17 + col] = mx.y;
    smn[(k0+2)*17 + col] = mn.z; smx[(k0+2)*17 + col] = mx.z;
    smn[(k0+3)*17 + col] = mn.w; smx[(k0+3)*17 + col] = mx.w;
    __syncthreads();
    if (t < 64) {
        float a = INFINITY, b = -INFINITY;
        #pragma unroll
        for (int c = 0; c < 16; ++c) {
            a = fminf(a, smn[t*17 + c]);
            b = fmaxf(b, smx[t*17 + c]);
        }
        atomicMinF(&g_amin[h*NK + t], a);
        atomicMaxF(&g_amax[h*NK + t], b);
    }
}

// ---------------- kernel 1b: min/max of B ------------------------------------
__global__ __launch_bounds__(480) void k_minmax_B(const float* __restrict__ B,
                                                  int batch, int bpb) {
    int h  = blockIdx.x;
    int b0 = blockIdx.y * bpb;
    int t  = threadIdx.x;
    float mn = INFINITY, mx = -INFINITY;
    for (int bi = 0; bi < bpb; ++bi) {
        int b = b0 + bi;
        if (b >= batch) break;
        const float* p = B + ((size_t)b * NH + h) * (NK*ND);
        #pragma unroll
        for (int it = 0; it < 4; ++it) {
            float v = p[it * 480 + t];
            mn = fminf(mn, v); mx = fmaxf(mx, v);
        }
    }
    __shared__ float smn[30*17], smx[30*17];
    int d = t % 30, g = t / 30;
    smn[d*17 + g] = mn; smx[d*17 + g] = mx;
    __syncthreads();
    if (t < 30) {
        float a = INFINITY, b = -INFINITY;
        #pragma unroll
        for (int c = 0; c < 16; ++c) {
            a = fminf(a, smn[t*17 + c]);
            b = fmaxf(b, smx[t*17 + c]);
        }
        atomicMinF(&g_bmin[h*ND + t], a);
        atomicMaxF(&g_bmax[h*ND + t], b);
    }
}

// ---------------- kernel 2: per-channel quant params -------------------------
__global__ void k_params() {
    int i = threadIdx.x;
    if (i < NH*NK) {
        float mn = g_amin[i], mx = g_amax[i];
        float d = fmaxf((mx - mn) / 255.0f, 1e-8f);
        float z = rintf(-mn / d);
        g_dA[i] = d; g_zA[i] = z; g_iA[i] = 1.0f / d;
    }
    if (i < NH*ND) {
        float mn = g_bmin[i], mx = g_bmax[i];
        float d = fmaxf((mx - mn) / 255.0f, 1e-8f);
        float z = rintf(-mn / d);
        g_dB[i] = d; g_zB[i] = z; g_iB[i] = 1.0f / d;
    }
}

// fake-quant (q-zp)*delta; magic-RNE fast path, tie rescue via true division
__device__ __forceinline__ float fq(float x, float dlt, float zp, float inv) {
    float y = x * inv;
    float r = rne(y);
    if (fabsf(fabsf(y - r) - 0.5f) < 1e-4f) r = rintf(x / dlt);
    float q = fminf(fmaxf(r + zp, 0.0f), 255.0f);
    return (q - zp) * dlt;
}
// fake-quant returning the integer (q-zp)  (exact fp32, low mantissa zero)
__device__ __forceinline__ float fqi(float x, float dlt, float zp, float inv) {
    float y = x * inv;
    float r = rne(y);
    if (fabsf(fabsf(y - r) - 0.5f) < 1e-4f) r = rintf(x / dlt);
    return fminf(fmaxf(r + zp, 0.0f), 255.0f) - zp;
}

// ---------------- per-slice smem layout (bytes) ------------------------------
// Ahi: 64 rows(m) x 128B (bf16, SW128 swizzled) = 8192
// Alo: 8192
// Bt : 32 rows(d) x 128B (bf16 ints, SW128)     = 4096   (rows 30,31 unused)
#define OFF_AHI 0
#define OFF_ALO 8192
#define OFF_BT  16384
#define SLICE_BYTES 20480
#define SMEM_DYN (2*SLICE_BYTES + 1024)

// ---------------- kernel 3: bf16 hi/lo split MMA quantized matmul ------------
// One block per PAIR of (b,h) slices; 8 warps, warps 0-3 slice0, 4-7 slice1.
__global__ __launch_bounds__(256)
void k_qmm_mma(const float* __restrict__ A, const float* __restrict__ B,
               float* __restrict__ C, int pair0) {
    extern __shared__ char raw[];
    char* sm = (char*)(((uintptr_t)raw + 1023) & ~(uintptr_t)1023);
    uint32_t sb = smem_to_u32(sm);

    int t = threadIdx.x;
    int p = blockIdx.x + pair0;
    int s0 = 2 * p;
    int h0 = s0 % NH, h1 = (s0 + 1) % NH;

    // ---- A: quantize, truncation hi/lo split, swizzled store ----
    const float4* Ap = (const float4*)(A + (size_t)s0 * (NN*NK));
    int k0 = (4 * t) & 63;
    #pragma unroll
    for (int j = 0; j < 2; ++j) {
        int hb = (j ? h1 : h0) * NK + k0;
        float4 d4 = __ldg((const float4*)&g_dA[hb]);
        float4 z4 = __ldg((const float4*)&g_zA[hb]);
        float4 i4 = __ldg((const float4*)&g_iA[hb]);
        char* base = sm + j * SLICE_BYTES;
        #pragma unroll
        for (int it = 0; it < 4; ++it) {
            int idx = (j * 4 + it) * 256 + t;
            float4 v = Ap[idx];
            int m = (idx & 1023) >> 4;
            float q0 = fq(v.x, d4.x, z4.x, i4.x);
            float q1 = fq(v.y, d4.y, z4.y, i4.y);
            float q2 = fq(v.z, d4.z, z4.z, i4.z);
            float q3 = fq(v.w, d4.w, z4.w, i4.w);
            // hi = truncate to bf16 (exact, LOP3); lo = exact residual
            uint32_t u0 = __float_as_uint(q0), u1 = __float_as_uint(q1);
            uint32_t u2 = __float_as_uint(q2), u3 = __float_as_uint(q3);
            uint32_t hi01 = __byte_perm(u0, u1, 0x7632);
            uint32_t hi23 = __byte_perm(u2, u3, 0x7632);
            float l0 = q0 - __uint_as_float(u0 & 0xFFFF0000u);
            float l1 = q1 - __uint_as_float(u1 & 0xFFFF0000u);
            float l2 = q2 - __uint_as_float(u2 & 0xFFFF0000u);
            float l3 = q3 - __uint_as_float(u3 & 0xFFFF0000u);
            uint32_t lo01, lo23;   // packed {lo, hi} = {l0, l1}, {l2, l3}
            asm("cvt.rn.bf16x2.f32 %0, %1, %2;" : "=r"(lo01) : "f"(l1), "f"(l0));
            asm("cvt.rn.bf16x2.f32 %0, %1, %2;" : "=r"(lo23) : "f"(l3), "f"(l2));
            uint32_t off = SWZ128((uint32_t)(m * 128 + k0 * 2));
            *(uint2*)(base + OFF_AHI + off) = make_uint2(hi01, hi23);
            *(uint2*)(base + OFF_ALO + off) = make_uint2(lo01, lo23);
        }
    }

    // ---- B: quantize to exact integers; bf16 = top 16 bits (no cvt) ----
    const float* Bp = B + (size_t)s0 * (NK*ND);
    #pragma unroll
    for (int it = 0; it < 15; ++it) {
        int e = it * 256 + t;
        float x = Bp[e];
        int j  = (e >= NK*ND);
        int e2 = e - j * (NK*ND);
        int k  = e2 / ND, d = e2 % ND;
        int hb = (j ? h1 : h0) * ND + d;
        float bi = fqi(x, __ldg(&g_dB[hb]), __ldg(&g_zB[hb]), __ldg(&g_iB[hb]));
        uint32_t off = SWZ128((uint32_t)(d * 128 + k * 2));
        *(uint16_t*)(sm + j * SLICE_BYTES + OFF_BT + off) =
            (uint16_t)(__float_as_uint(bi) >> 16);
    }
    __syncthreads();

    // ---- compute: warp = 16 rows x 32 cols, mma.sync m16n8k16 bf16 ----
    int w = t >> 5, lane = t & 31;
    int sj = w >> 2;          // slice
    int ws = w & 3;           // warp within slice
    int r0 = ws * 16;
    uint32_t baseS = sb + sj * SLICE_BYTES;

    int la = lane & 7, lb = (lane >> 3) & 1, lc = (lane >> 4) & 1;
    uint32_t aRel = (uint32_t)((r0 + la + lb * 8) * 128 + lc * 16);
    uint32_t bRel = (uint32_t)((la + lc * 8) * 128 + lb * 16);

    float acc[4][4];
    #pragma unroll
    for (int i = 0; i < 4; ++i)
        #pragma unroll
        for (int q = 0; q < 4; ++q) acc[i][q] = 0.0f;

    #pragma unroll
    for (int kt = 0; kt < 4; ++kt) {
        uint32_t ko = kt * 32;
        uint32_t ah[4], al[4], b0[4], b1[4];
        uint32_t ao = SWZ128(aRel + ko);
        ldsm_x4(ah, baseS + OFF_AHI + ao);
        ldsm_x4(al, baseS + OFF_ALO + ao);
        ldsm_x4(b0, baseS + OFF_BT + SWZ128(bRel + ko));            // d 0..15
        ldsm_x4(b1, baseS + OFF_BT + SWZ128(bRel + 2048 + ko));     // d 16..31
        mma_bf16(acc[0], ah, b0 + 0); mma_bf16(acc[0], al, b0 + 0);
        mma_bf16(acc[1], ah, b0 + 2); mma_bf16(acc[1], al, b0 + 2);
        mma_bf16(acc[2], ah, b1 + 0); mma_bf16(acc[2], al, b1 + 0);
        mma_bf16(acc[3], ah, b1 + 2); mma_bf16(acc[3], al, b1 + 2);
    }

    // ---- epilogue: scale by dB[d], float2 writes ----
    int s  = s0 + sj;
    int h  = s % NH;
    int row = r0 + (lane >> 2);
    int dd  = 2 * (lane & 3);
    float* Cp = C + (size_t)s * (NN*ND);
    #pragma unroll
    for (int nt = 0; nt < 4; ++nt) {
        int d = nt * 8 + dd;
        if (d < ND) {
            float sc0 = __ldg(&g_dB[h*ND + d]);
            float sc1 = __ldg(&g_dB[h*ND + d + 1]);   // d+1 <= 29 whenever d < 30
            *(float2*)(Cp + row * ND + d) =
                make_float2(acc[nt][0] * sc0, acc[nt][1] * sc1);
            *(float2*)(Cp + (row + 8) * ND + d) =
                make_float2(acc[nt][2] * sc0, acc[nt][3] * sc1);
        }
    }
}

// ---------------- launch -----------------------------------------------------
extern "C" void kernel_launch(void* const* d_in, const int* in_sizes, int n_in,
                              void* d_out, int out_size) {
    const float* A = (const float*)d_in[0];
    const float* B = (const float*)d_in[1];
    float* C = (float*)d_out;

    int batch  = in_sizes[0] / (NH * NN * NK);   // 4096
    int npairs = batch * NH / 2;                 // 12288

    k_init<<<1, 384>>>();

    int bpbA = 16;
    int nbyA = (batch + bpbA - 1) / bpbA;
    k_minmax_A<<<dim3(NH, nbyA), 256>>>(A, batch, bpbA);

    int bpbB = 32;
    int nbyB = (batch + bpbB - 1) / bpbB;
    k_minmax_B<<<dim3(NH, nbyB), 480>>>(B, batch, bpbB);

    k_params<<<1, 384>>>();

    cudaFuncSetAttribute(k_qmm_mma, cudaFuncAttributeMaxDynamicSharedMemorySize,
                         SMEM_DYN);
    // split into two launches (also puts the 6th launch on qmm for ncu -s 5)
    int half = npairs / 2;
    k_qmm_mma<<<half, 256, SMEM_DYN>>>(A, B, C, 0);
    k_qmm_mma<<<npairs - half, 256, SMEM_DYN>>>(A, B, C, half);
}